// round 2
// baseline (speedup 1.0000x reference)
#include <cuda_runtime.h>
#include <math.h>

constexpr int B_ = 2, S_ = 4096, HID_ = 2048, NVH_ = 32;
constexpr int CONV_ = 8192, KEY_ = 2048, VAL_ = 4096;
constexpr int NC_ = 64, BH_ = 64, MROWS = 8192;

static __device__ float g_lin  [(size_t)MROWS*CONV_];
static __device__ float g_conv [(size_t)MROWS*CONV_];
static __device__ float g_z    [(size_t)MROWS*VAL_];
static __device__ float g_beta [(size_t)MROWS*NVH_];
static __device__ float g_gg   [(size_t)MROWS*NVH_];
static __device__ float g_qg   [(size_t)BH_*S_*128];
static __device__ float g_kdd  [(size_t)BH_*S_*128];
static __device__ float g_vc   [(size_t)BH_*S_*128];
static __device__ float g_kcd  [(size_t)BH_*S_*128];
static __device__ float g_attn [(size_t)BH_*NC_*64*64];
static __device__ float g_glast[BH_*NC_];
static __device__ float g_o    [(size_t)BH_*S_*128];
static __device__ float g_y    [(size_t)MROWS*VAL_];

__device__ __forceinline__ float siluf(float v){ return v / (1.f + expf(-v)); }

// ---------------- SGEMM: C[M,N]=A[M,K]@B[K,N], row-major, 128x128x16 ----
__global__ __launch_bounds__(256) void sgemm128(
    const float* __restrict__ A, const float* __restrict__ B,
    float* __restrict__ C, int M, int N, int K)
{
    __shared__ float As[2][16][128];
    __shared__ float Bs[2][16][128];
    const int tid = threadIdx.x, tx = tid & 15, ty = tid >> 4;
    const int bx = blockIdx.x * 128, by = blockIdx.y * 128;
    const int arow = tid >> 2, acol = (tid & 3) << 2;
    const int brow = tid >> 5, bcol = (tid & 31) << 2;
    const float* Ag = A + (size_t)(by + arow) * K + acol;
    const float* Bg = B + (size_t)brow * N + bx + bcol;
    const int nt = K >> 4;
    float4 av0 = *(const float4*)Ag;
    float4 av1 = *(const float4*)(Ag + (size_t)64 * K);
    float4 bv0 = *(const float4*)Bg;
    float4 bv1 = *(const float4*)(Bg + (size_t)8 * N);
    As[0][acol+0][arow]=av0.x; As[0][acol+1][arow]=av0.y;
    As[0][acol+2][arow]=av0.z; As[0][acol+3][arow]=av0.w;
    As[0][acol+0][arow+64]=av1.x; As[0][acol+1][arow+64]=av1.y;
    As[0][acol+2][arow+64]=av1.z; As[0][acol+3][arow+64]=av1.w;
    *(float4*)&Bs[0][brow][bcol]=bv0; *(float4*)&Bs[0][brow+8][bcol]=bv1;
    __syncthreads();
    float acc[8][8];
    #pragma unroll
    for (int m=0;m<8;m++){ 
        #pragma unroll
        for(int n=0;n<8;n++) acc[m][n]=0.f; }
    for (int kt=0; kt<nt; kt++) {
        const int cur = kt&1, nxt = cur^1;
        if (kt+1 < nt) {
            const float* A2 = Ag + ((kt+1)<<4);
            const float* B2 = Bg + (size_t)((kt+1)<<4) * N;
            av0=*(const float4*)A2; av1=*(const float4*)(A2+(size_t)64*K);
            bv0=*(const float4*)B2; bv1=*(const float4*)(B2+(size_t)8*N);
        }
        #pragma unroll
        for (int k=0;k<16;k++) {
            float4 a0=*(const float4*)&As[cur][k][ty*4];
            float4 a1=*(const float4*)&As[cur][k][64+ty*4];
            float4 b0=*(const float4*)&Bs[cur][k][tx*4];
            float4 b1=*(const float4*)&Bs[cur][k][64+tx*4];
            float af[8]={a0.x,a0.y,a0.z,a0.w,a1.x,a1.y,a1.z,a1.w};
            float bf[8]={b0.x,b0.y,b0.z,b0.w,b1.x,b1.y,b1.z,b1.w};
            #pragma unroll
            for (int m=0;m<8;m++){
                #pragma unroll
                for(int n=0;n<8;n++) acc[m][n]=fmaf(af[m],bf[n],acc[m][n]); }
        }
        if (kt+1 < nt) {
            As[nxt][acol+0][arow]=av0.x; As[nxt][acol+1][arow]=av0.y;
            As[nxt][acol+2][arow]=av0.z; As[nxt][acol+3][arow]=av0.w;
            As[nxt][acol+0][arow+64]=av1.x; As[nxt][acol+1][arow+64]=av1.y;
            As[nxt][acol+2][arow+64]=av1.z; As[nxt][acol+3][arow+64]=av1.w;
            *(float4*)&Bs[nxt][brow][bcol]=bv0; *(float4*)&Bs[nxt][brow+8][bcol]=bv1;
        }
        __syncthreads();
    }
    float* Cg = C + (size_t)by * N + bx;
    #pragma unroll
    for (int r=0;r<8;r++) {
        const int m = (r<4) ? (ty*4+r) : (64+ty*4+r-4);
        float4 w0={acc[r][0],acc[r][1],acc[r][2],acc[r][3]};
        float4 w1={acc[r][4],acc[r][5],acc[r][6],acc[r][7]};
        *(float4*)(Cg+(size_t)m*N+tx*4)=w0;
        *(float4*)(Cg+(size_t)m*N+64+tx*4)=w1;
    }
}

// ---------------- beta = sigmoid(x@w_b); g = -exp(a_log)*softplus(x@w_a+dt)
__global__ __launch_bounds__(256) void kc_beta_g(
    const float* __restrict__ x, const float* __restrict__ wb,
    const float* __restrict__ wa, const float* __restrict__ dtb,
    const float* __restrict__ alog, float* __restrict__ beta, float* __restrict__ g)
{
    __shared__ float xs[4*HID_];
    const int r0 = blockIdx.x * 4;
    for (int t = threadIdx.x; t < 4*HID_; t += 256)
        xs[t] = x[(size_t)r0*HID_ + t];
    __syncthreads();
    const int row = threadIdx.x >> 6, j = threadIdx.x & 63, col = j & 31;
    const float* w = (j < 32) ? wb : wa;
    float acc = 0.f;
    const float* xr = xs + row*HID_;
    for (int k = 0; k < HID_; k++) acc = fmaf(xr[k], w[(size_t)k*32+col], acc);
    const size_t oi = (size_t)(r0+row)*NVH_ + col;
    if (j < 32) beta[oi] = 1.f/(1.f+expf(-acc));
    else {
        float aa = acc + dtb[col];
        float sp = fmaxf(aa,0.f) + log1pf(expf(-fabsf(aa)));
        g[oi] = -expf(alog[col]) * sp;
    }
}

// ---------------- causal depthwise conv (KS=4) + silu --------------------
__global__ __launch_bounds__(256) void kd_conv(
    const float* __restrict__ lin, const float* __restrict__ cw, float* __restrict__ out)
{
    const size_t idx = (size_t)blockIdx.x*256 + threadIdx.x;  // over MROWS*CONV/4
    const int d4 = (int)(idx & (CONV_/4 - 1));
    const size_t bs = idx >> 11;
    const int s = (int)(bs & (S_-1));
    const int d0 = d4*4;
    float w0[4],w1[4],w2[4],w3[4];
    *(float4*)w0 = ((const float4*)cw)[d0+0];
    *(float4*)w1 = ((const float4*)cw)[d0+1];
    *(float4*)w2 = ((const float4*)cw)[d0+2];
    *(float4*)w3 = ((const float4*)cw)[d0+3];
    float a0=0,a1=0,a2=0,a3=0;
    #pragma unroll
    for (int t=0;t<4;t++) {
        if (s-3+t >= 0) {
            const float4 xv = *(const float4*)(lin + (bs+t-3)*CONV_ + d0);
            a0=fmaf(xv.x,w0[t],a0); a1=fmaf(xv.y,w1[t],a1);
            a2=fmaf(xv.z,w2[t],a2); a3=fmaf(xv.w,w3[t],a3);
        }
    }
    float4 r; r.x=siluf(a0); r.y=siluf(a1); r.z=siluf(a2); r.w=siluf(a3);
    ((float4*)out)[idx] = r;
}

// ---------------- per-chunk precompute (one CTA per (b,h,chunk)) ---------
constexpr int KE_SMEM = (3*64*129 + 64*64 + 64*65 + 192) * 4;
__global__ __launch_bounds__(256) void ke_pre(
    const float* __restrict__ conv, const float* __restrict__ betag,
    const float* __restrict__ gin, float* __restrict__ qg, float* __restrict__ kdo,
    float* __restrict__ vco, float* __restrict__ kcdo, float* __restrict__ attnl,
    float* __restrict__ glasto)
{
    extern __shared__ float sm[];
    float* q_s  = sm;                 // [64][129]
    float* k_s  = q_s + 64*129;
    float* vb_s = k_s + 64*129;
    float* A_s  = vb_s + 64*129;      // [64][64]
    float* T_s  = A_s + 64*64;        // [64][65]
    float* gc_s = T_s + 64*65;        // [64]
    float* be_s = gc_s + 64;
    float* w_s  = be_s + 64;
    const int blk = blockIdx.x;
    const int n = blk & 63, h = (blk>>6) & 31, b = blk >> 11, kh = h >> 1;
    const int s0 = n*64, tid = threadIdx.x;
    const size_t rowbase = ((size_t)(b*S_)+s0)*CONV_;
    for (int t = tid; t < 64*128; t += 256) {
        const int i = t>>7, c = t&127;
        const size_t base = rowbase + (size_t)i*CONV_;
        q_s [i*129+c] = conv[base + kh*128 + c];
        k_s [i*129+c] = conv[base + KEY_ + kh*128 + c];
        vb_s[i*129+c] = conv[base + 2*KEY_ + h*128 + c];
    }
    if (tid < 64) {
        const size_t gi = ((size_t)(b*S_)+s0+tid)*NVH_ + h;
        be_s[tid] = betag[gi];
        gc_s[tid] = gin[gi];
    }
    __syncthreads();
    if (tid == 0) {
        float run = 0.f;
        for (int i = 0; i < 64; i++) { run += gc_s[i]; gc_s[i] = run; }
        glasto[blk] = run;
    }
    __syncthreads();
    { // l2norm q,k; q *= 128^-0.5
        const int warp = tid >> 5, lane = tid & 31;
        for (int rr = 0; rr < 2; rr++) {
            const int i = warp*2 + rr + ((tid>=256)?0:0);
            (void)i;
        }
        for (int rr = 0; rr < 8; rr++) {
            const int i = warp*8 + rr;
            float qv[4], kv[4]; float sq=0.f, sk=0.f;
            #pragma unroll
            for (int u=0;u<4;u++){
                const int c = lane + u*32;
                qv[u]=q_s[i*129+c]; kv[u]=k_s[i*129+c];
                sq=fmaf(qv[u],qv[u],sq); sk=fmaf(kv[u],kv[u],sk);
            }
            #pragma unroll
            for (int off=16; off; off>>=1) {
                sq += __shfl_xor_sync(0xffffffffu, sq, off);
                sk += __shfl_xor_sync(0xffffffffu, sk, off);
            }
            const float iq = rsqrtf(sq+1e-6f)*0.08838834764831845f;
            const float ik = rsqrtf(sk+1e-6f);
            #pragma unroll
            for (int u=0;u<4;u++){
                const int c = lane + u*32;
                q_s[i*129+c]=qv[u]*iq; k_s[i*129+c]=kv[u]*ik;
            }
        }
    }
    for (int t = tid; t < 64*128; t += 256) {
        const int i = t>>7, c = t&127;
        vb_s[i*129+c] *= be_s[i];
    }
    for (int t = tid; t < 64*65; t += 256) T_s[t] = 0.f;
    if (tid < 64) w_s[tid] = be_s[tid]*expf(gc_s[tid]);
    __syncthreads();
    { // A (strict lower) and local attn (lower incl diag)
        const int ti = tid >> 4, tj = tid & 15;
        const int i0 = ti*4, j0 = tj*4;
        float dk[4][4], dq[4][4];
        #pragma unroll
        for (int r=0;r<4;r++){
            #pragma unroll
            for(int u=0;u<4;u++){dk[r][u]=0.f;dq[r][u]=0.f;} }
        for (int c = 0; c < 128; c++) {
            float ki[4],qi[4],kj[4];
            #pragma unroll
            for (int r=0;r<4;r++){ ki[r]=k_s[(i0+r)*129+c]; qi[r]=q_s[(i0+r)*129+c]; kj[r]=k_s[(j0+r)*129+c]; }
            #pragma unroll
            for (int r=0;r<4;r++){
                #pragma unroll
                for(int u=0;u<4;u++){ dk[r][u]=fmaf(ki[r],kj[u],dk[r][u]); dq[r][u]=fmaf(qi[r],kj[u],dq[r][u]); } }
        }
        const size_t ab = (size_t)blk*4096;
        #pragma unroll
        for (int r=0;r<4;r++){
            #pragma unroll
            for (int u=0;u<4;u++){
                const int i=i0+r, j=j0+u;
                const float dec = (i>=j) ? expf(gc_s[i]-gc_s[j]) : 0.f;
                A_s[i*64+j] = (i>j) ? (-be_s[i]*dk[r][u]*dec) : 0.f;
                attnl[ab + i*64 + j] = (i>=j) ? dq[r][u]*dec : 0.f;
            }
        }
    }
    __syncthreads();
    if (tid < 64) { // T = (I-A)^{-1}, forward substitution, one column each
        const int col = tid;
        T_s[col*65+col] = 1.f;
        for (int i = col+1; i < 64; i++) {
            float acc = 0.f;
            for (int j = col; j < i; j++) acc = fmaf(A_s[i*64+j], T_s[j*65+col], acc);
            T_s[i*65+col] = acc;
        }
    }
    __syncthreads();
    { // v_c = T @ v_beta,  kcd = (T .* w_j) @ k
        const int it = tid >> 4, ct = tid & 15;
        const int i0 = it*4, c0 = ct*8;
        float avc[4][8], akc[4][8];
        #pragma unroll
        for (int r=0;r<4;r++){
            #pragma unroll
            for(int u=0;u<8;u++){avc[r][u]=0.f;akc[r][u]=0.f;} }
        for (int j = 0; j < 64; j++) {
            float tj4[4], tw4[4];
            const float wj = w_s[j];
            #pragma unroll
            for (int r=0;r<4;r++){ tj4[r]=T_s[(i0+r)*65+j]; tw4[r]=tj4[r]*wj; }
            #pragma unroll
            for (int u=0;u<8;u++){
                const float vbv = vb_s[j*129+c0+u];
                const float kv  = k_s [j*129+c0+u];
                #pragma unroll
                for (int r=0;r<4;r++){
                    avc[r][u]=fmaf(tj4[r],vbv,avc[r][u]);
                    akc[r][u]=fmaf(tw4[r],kv ,akc[r][u]);
                }
            }
        }
        const size_t cb = (size_t)blk*8192;
        #pragma unroll
        for (int r=0;r<4;r++){
            #pragma unroll
            for (int u=0;u<8;u++){
                vco [cb + (i0+r)*128 + c0+u] = avc[r][u];
                kcdo[cb + (i0+r)*128 + c0+u] = akc[r][u];
            }
        }
    }
    { // qg = q*exp(gc); kd = k*exp(gl-gc)
        const float gl = gc_s[63];
        const size_t cb = (size_t)blk*8192;
        for (int t = tid; t < 64*128; t += 256) {
            const int i = t>>7, c = t&127;
            qg [cb+t] = q_s[i*129+c]*expf(gc_s[i]);
            kdo[cb+t] = k_s[i*129+c]*expf(gl-gc_s[i]);
        }
    }
}

// ---------------- persistent V-split scan (128 CTAs) ---------------------
constexpr int SCAN_SMEM = (128*64 + 3*64*128 + 2*64*64) * 4;  // 163840
__global__ __launch_bounds__(256) void kf_scan(
    const float* __restrict__ qg, const float* __restrict__ kcd,
    const float* __restrict__ kd, const float* __restrict__ vc,
    const float* __restrict__ attn, const float* __restrict__ glast,
    float* __restrict__ o)
{
    extern __shared__ float sm[];
    float* st    = sm;             // [128][64]
    float* qg_s  = st + 8192;      // [64][128]
    float* kcd_s = qg_s + 8192;
    float* kd_s  = kcd_s + 8192;
    float* at_s  = kd_s + 8192;    // [64][64]
    float* vn_s  = at_s + 4096;    // [64][64]
    const int cta = blockIdx.x, vh = cta & 1, bh = cta >> 1;
    const int tid = threadIdx.x;
    const int ti = tid >> 4, tj = tid & 15;
    const int i0 = ti*4, c0 = tj*4, k0 = ti*8;
    for (int t = tid; t < 8192; t += 256) st[t] = 0.f;
    __syncthreads();
    for (int n = 0; n < 64; n++) {
        const size_t blk = (size_t)(bh*64 + n);
        const float4* qgg = (const float4*)(qg + blk*8192);
        const float4* kcg = (const float4*)(kcd + blk*8192);
        const float4* kdg = (const float4*)(kd + blk*8192);
        for (int t = tid; t < 2048; t += 256) {
            ((float4*)qg_s)[t]=qgg[t]; ((float4*)kcd_s)[t]=kcg[t]; ((float4*)kd_s)[t]=kdg[t];
        }
        const float4* atg = (const float4*)(attn + blk*4096);
        for (int t = tid; t < 1024; t += 256) ((float4*)at_s)[t] = atg[t];
        for (int t = tid; t < 1024; t += 256) {
            const int i = t>>4, cg = (t&15)*4;
            *(float4*)(vn_s + i*64 + cg) = *(const float4*)(vc + blk*8192 + i*128 + vh*64 + cg);
        }
        __syncthreads();
        // phase A: ov = qg@st, vv = kcd@st
        float ov[4][4], vv[4][4];
        #pragma unroll
        for (int r=0;r<4;r++){
            #pragma unroll
            for(int u=0;u<4;u++){ov[r][u]=0.f;vv[r][u]=0.f;} }
        for (int k = 0; k < 128; k++) {
            const float4 sv = *(const float4*)&st[k*64 + c0];
            #pragma unroll
            for (int r=0;r<4;r++) {
                const float kq = qg_s[(i0+r)*128+k];
                const float kc = kcd_s[(i0+r)*128+k];
                ov[r][0]=fmaf(kq,sv.x,ov[r][0]); ov[r][1]=fmaf(kq,sv.y,ov[r][1]);
                ov[r][2]=fmaf(kq,sv.z,ov[r][2]); ov[r][3]=fmaf(kq,sv.w,ov[r][3]);
                vv[r][0]=fmaf(kc,sv.x,vv[r][0]); vv[r][1]=fmaf(kc,sv.y,vv[r][1]);
                vv[r][2]=fmaf(kc,sv.z,vv[r][2]); vv[r][3]=fmaf(kc,sv.w,vv[r][3]);
            }
        }
        // v_new = v_c - vv (each thread owns its cells)
        #pragma unroll
        for (int r=0;r<4;r++){
            #pragma unroll
            for(int u=0;u<4;u++) vn_s[(i0+r)*64 + c0+u] -= vv[r][u]; }
        __syncthreads();
        // phase B: ov += attn @ v_new, write o
        for (int j = 0; j < 64; j++) {
            const float4 vj = *(const float4*)&vn_s[j*64 + c0];
            #pragma unroll
            for (int r=0;r<4;r++) {
                const float a = at_s[(i0+r)*64+j];
                ov[r][0]=fmaf(a,vj.x,ov[r][0]); ov[r][1]=fmaf(a,vj.y,ov[r][1]);
                ov[r][2]=fmaf(a,vj.z,ov[r][2]); ov[r][3]=fmaf(a,vj.w,ov[r][3]);
            }
        }
        float* og = o + blk*8192 + vh*64;
        #pragma unroll
        for (int r=0;r<4;r++)
            *(float4*)(og + (i0+r)*128 + c0) = make_float4(ov[r][0],ov[r][1],ov[r][2],ov[r][3]);
        // phase C: state = state*exp(gl) + kd^T @ v_new
        const float eg = expf(glast[blk]);
        float sa[8][4];
        #pragma unroll
        for (int r=0;r<8;r++){
            #pragma unroll
            for(int u=0;u<4;u++) sa[r][u]=0.f; }
        for (int i = 0; i < 64; i++) {
            const float4 vi = *(const float4*)&vn_s[i*64 + c0];
            #pragma unroll
            for (int r=0;r<8;r++) {
                const float kv = kd_s[i*128 + k0 + r];
                sa[r][0]=fmaf(kv,vi.x,sa[r][0]); sa[r][1]=fmaf(kv,vi.y,sa[r][1]);
                sa[r][2]=fmaf(kv,vi.z,sa[r][2]); sa[r][3]=fmaf(kv,vi.w,sa[r][3]);
            }
        }
        #pragma unroll
        for (int r=0;r<8;r++){
            #pragma unroll
            for (int u=0;u<4;u++) {
                float* p = &st[(k0+r)*64 + c0+u];
                *p = (*p)*eg + sa[r][u];
            }
        }
        __syncthreads();
    }
}

// ---------------- gated RMSNorm ------------------------------------------
__global__ __launch_bounds__(256) void kg_norm(
    const float* __restrict__ o, const float* __restrict__ z,
    const float* __restrict__ nw, float* __restrict__ y)
{
    const int gw = (blockIdx.x*256 + threadIdx.x) >> 5;
    const int lane = threadIdx.x & 31;
    const int h = gw & 31, bs = gw >> 5;
    const int b = bs >> 12, s = bs & 4095;
    const size_t oi = (((size_t)(b*32+h)*64 + (s>>6))*64 + (s&63))*128;
    const float4 cv = *(const float4*)(o + oi + lane*4);
    float ss = cv.x*cv.x + cv.y*cv.y + cv.z*cv.z + cv.w*cv.w;
    #pragma unroll
    for (int off=16; off; off>>=1) ss += __shfl_xor_sync(0xffffffffu, ss, off);
    const float inv = rsqrtf(ss*(1.f/128.f) + 1e-6f);
    const float4 zv = *(const float4*)(z + (size_t)bs*4096 + h*128 + lane*4);
    const float4 w  = *(const float4*)(nw + lane*4);
    float4 r;
    r.x = cv.x*inv*w.x*siluf(zv.x); r.y = cv.y*inv*w.y*siluf(zv.y);
    r.z = cv.z*inv*w.z*siluf(zv.z); r.w = cv.w*inv*w.w*siluf(zv.w);
    *(float4*)(y + (size_t)bs*4096 + h*128 + lane*4) = r;
}

// ---------------- launch ---------------------------------------------------
extern "C" void kernel_launch(void* const* d_in, const int* in_sizes, int n_in,
                              void* d_out, int out_size)
{
    const float* x     = (const float*)d_in[0];
    const float* w_qkv = (const float*)d_in[1];
    const float* w_z   = (const float*)d_in[2];
    const float* w_b   = (const float*)d_in[3];
    const float* w_a   = (const float*)d_in[4];
    const float* cw    = (const float*)d_in[5];
    const float* dtb   = (const float*)d_in[6];
    const float* alog  = (const float*)d_in[7];
    const float* nw    = (const float*)d_in[8];
    const float* w_out = (const float*)d_in[9];
    float* out = (float*)d_out;

    float *lin,*conv,*z,*beta,*gg,*qg,*kdd,*vc,*kcd,*attn,*glast,*o,*y;
    cudaGetSymbolAddress((void**)&lin,  g_lin);
    cudaGetSymbolAddress((void**)&conv, g_conv);
    cudaGetSymbolAddress((void**)&z,    g_z);
    cudaGetSymbolAddress((void**)&beta, g_beta);
    cudaGetSymbolAddress((void**)&gg,   g_gg);
    cudaGetSymbolAddress((void**)&qg,   g_qg);
    cudaGetSymbolAddress((void**)&kdd,  g_kdd);
    cudaGetSymbolAddress((void**)&vc,   g_vc);
    cudaGetSymbolAddress((void**)&kcd,  g_kcd);
    cudaGetSymbolAddress((void**)&attn, g_attn);
    cudaGetSymbolAddress((void**)&glast,g_glast);
    cudaGetSymbolAddress((void**)&o,    g_o);
    cudaGetSymbolAddress((void**)&y,    g_y);

    cudaFuncSetAttribute(ke_pre,  cudaFuncAttributeMaxDynamicSharedMemorySize, KE_SMEM);
    cudaFuncSetAttribute(kf_scan, cudaFuncAttributeMaxDynamicSharedMemorySize, SCAN_SMEM);

    sgemm128<<<dim3(CONV_/128, MROWS/128), 256>>>(x, w_qkv, lin, MROWS, CONV_, HID_);
    sgemm128<<<dim3(VAL_/128,  MROWS/128), 256>>>(x, w_z,   z,   MROWS, VAL_, HID_);
    kc_beta_g<<<MROWS/4, 256>>>(x, w_b, w_a, dtb, alog, beta, gg);
    kd_conv<<<(MROWS*(CONV_/4))/256, 256>>>(lin, cw, conv);
    ke_pre<<<4096, 256, KE_SMEM>>>(conv, beta, gg, qg, kdd, vc, kcd, attn, glast);
    kf_scan<<<128, 256, SCAN_SMEM>>>(qg, kcd, kdd, vc, attn, glast, o);
    kg_norm<<<(MROWS*NVH_)/8, 256>>>(o, z, nw, y);
    sgemm128<<<dim3(HID_/128, MROWS/128), 256>>>(y, w_out, out, MROWS, HID_, VAL_);
}

// round 5
// speedup vs baseline: 1.1370x; 1.1370x over previous
#include <cuda_runtime.h>
#include <math.h>
#include <stdint.h>

constexpr int B_ = 2, S_ = 4096, HID_ = 2048, NVH_ = 32;
constexpr int CONV_ = 8192, KEY_ = 2048, VAL_ = 4096;
constexpr int NC_ = 64, BH_ = 64, MROWS = 8192;

static __device__ float g_lin  [(size_t)MROWS*CONV_];
static __device__ float g_conv [(size_t)MROWS*CONV_];
static __device__ float g_z    [(size_t)MROWS*VAL_];
static __device__ float g_beta [(size_t)MROWS*NVH_];
static __device__ float g_gg   [(size_t)MROWS*NVH_];
static __device__ float g_qg   [(size_t)BH_*S_*128];
static __device__ float g_kdd  [(size_t)BH_*S_*128];
static __device__ float g_vc   [(size_t)BH_*S_*128];
static __device__ float g_kcd  [(size_t)BH_*S_*128];
static __device__ float g_attn [(size_t)BH_*NC_*64*64];
static __device__ float g_glast[BH_*NC_];
static __device__ float g_o    [(size_t)BH_*S_*128];
static __device__ float g_y    [(size_t)MROWS*VAL_];
static __device__ float g_xt   [(size_t)MROWS*HID_];
static __device__ float g_wqkvT[(size_t)CONV_*HID_];
static __device__ float g_wzT  [(size_t)VAL_*HID_];
static __device__ float g_woutT[(size_t)HID_*VAL_];

__device__ __forceinline__ float siluf(float v){ return v / (1.f + expf(-v)); }
__device__ __forceinline__ float tf32r(float v){
    uint32_t o; asm("cvt.rna.tf32.f32 %0, %1;" : "=r"(o) : "f"(v));
    return __uint_as_float(o);
}
__device__ __forceinline__ void mma_tf32(float* c, const uint32_t* a, const uint32_t* b){
    asm volatile("mma.sync.aligned.m16n8k8.row.col.f32.tf32.tf32.f32 "
        "{%0,%1,%2,%3}, {%4,%5,%6,%7}, {%8,%9}, {%0,%1,%2,%3};"
        : "+f"(c[0]), "+f"(c[1]), "+f"(c[2]), "+f"(c[3])
        : "r"(a[0]), "r"(a[1]), "r"(a[2]), "r"(a[3]), "r"(b[0]), "r"(b[1]));
}

// ------- tf32 mma.sync GEMM: C[M,N] = A[M,K] @ Bt[N,K]^T, 128x128x16 ------
__global__ __launch_bounds__(256) void gemm_mma(
    const float* __restrict__ A, const float* __restrict__ Bt,
    float* __restrict__ C, int M, int N, int K)
{
    __shared__ float As[2][128][20];
    __shared__ float Bs[2][128][20];
    const int tid = threadIdx.x;
    const int bx = blockIdx.x * 128, by = blockIdx.y * 128;
    const int warp = tid >> 5, lane = tid & 31;
    const int gid = lane >> 2, tig = lane & 3;
    const int wm = (warp >> 2) * 64;      // 0 or 64
    const int wn = (warp & 3) * 32;       // 0,32,64,96
    const int lrow = tid >> 2;            // 0..63
    const int lk   = (tid & 3) * 4;       // 0,4,8,12
    const float* Ag = A  + (size_t)(by + lrow) * K + lk;
    const float* Bg = Bt + (size_t)(bx + lrow) * K + lk;
    const int NT = K >> 4;

    float acc[4][4][4];
    #pragma unroll
    for (int mt=0;mt<4;mt++){
        #pragma unroll
        for (int nt=0;nt<4;nt++){
            #pragma unroll
            for (int u=0;u<4;u++) acc[mt][nt][u]=0.f; } }

    float4 pa0 = *(const float4*)(Ag);
    float4 pa1 = *(const float4*)(Ag + (size_t)64 * K);
    float4 pb0 = *(const float4*)(Bg);
    float4 pb1 = *(const float4*)(Bg + (size_t)64 * K);
    *(float4*)&As[0][lrow   ][lk] = pa0;
    *(float4*)&As[0][lrow+64][lk] = pa1;
    *(float4*)&Bs[0][lrow   ][lk] = pb0;
    *(float4*)&Bs[0][lrow+64][lk] = pb1;
    __syncthreads();

    for (int kc = 0; kc < NT; kc++) {
        const int cur = kc & 1, nxt = cur ^ 1;
        if (kc + 1 < NT) {
            const float* A2 = Ag + (kc+1)*16;
            const float* B2 = Bg + (kc+1)*16;
            pa0 = *(const float4*)(A2);
            pa1 = *(const float4*)(A2 + (size_t)64 * K);
            pb0 = *(const float4*)(B2);
            pb1 = *(const float4*)(B2 + (size_t)64 * K);
        }
        #pragma unroll
        for (int kk = 0; kk < 2; kk++) {
            const int kb = kk * 8;
            uint32_t af[4][4], bf[4][2];
            #pragma unroll
            for (int mt = 0; mt < 4; mt++) {
                const int r = wm + mt*16 + gid;
                af[mt][0] = __float_as_uint(As[cur][r  ][kb + tig]);
                af[mt][1] = __float_as_uint(As[cur][r+8][kb + tig]);
                af[mt][2] = __float_as_uint(As[cur][r  ][kb + tig + 4]);
                af[mt][3] = __float_as_uint(As[cur][r+8][kb + tig + 4]);
            }
            #pragma unroll
            for (int nt = 0; nt < 4; nt++) {
                const int n = wn + nt*8 + gid;
                bf[nt][0] = __float_as_uint(Bs[cur][n][kb + tig]);
                bf[nt][1] = __float_as_uint(Bs[cur][n][kb + tig + 4]);
            }
            #pragma unroll
            for (int mt = 0; mt < 4; mt++){
                #pragma unroll
                for (int nt = 0; nt < 4; nt++)
                    mma_tf32(acc[mt][nt], af[mt], bf[nt]);
            }
        }
        if (kc + 1 < NT) {
            *(float4*)&As[nxt][lrow   ][lk] = pa0;
            *(float4*)&As[nxt][lrow+64][lk] = pa1;
            *(float4*)&Bs[nxt][lrow   ][lk] = pb0;
            *(float4*)&Bs[nxt][lrow+64][lk] = pb1;
        }
        __syncthreads();
    }

    #pragma unroll
    for (int mt = 0; mt < 4; mt++) {
        const int r0 = by + wm + mt*16 + gid;
        #pragma unroll
        for (int nt = 0; nt < 4; nt++) {
            const int cc = bx + wn + nt*8 + tig*2;
            *(float2*)(C + (size_t)r0 * N + cc)     = make_float2(acc[mt][nt][0], acc[mt][nt][1]);
            *(float2*)(C + (size_t)(r0+8) * N + cc) = make_float2(acc[mt][nt][2], acc[mt][nt][3]);
        }
    }
}

// ---------------- weight transpose + tf32 round: w[K,N] -> wt[N,K] --------
__global__ __launch_bounds__(256) void kt_trans(
    const float* __restrict__ w, float* __restrict__ wt, int K, int N)
{
    __shared__ float t[32][33];
    const int tx = threadIdx.x & 31, ty = threadIdx.x >> 5;
    const int n0 = blockIdx.x * 32, k0 = blockIdx.y * 32;
    #pragma unroll
    for (int r = 0; r < 4; r++)
        t[ty + r*8][tx] = w[(size_t)(k0 + ty + r*8) * N + n0 + tx];
    __syncthreads();
    #pragma unroll
    for (int r = 0; r < 4; r++)
        wt[(size_t)(n0 + ty + r*8) * K + k0 + tx] = tf32r(t[tx][ty + r*8]);
}

// ---------------- tf32 round x --------------------------------------------
__global__ __launch_bounds__(256) void kt_round(const float* __restrict__ x, float* __restrict__ xt)
{
    const size_t i = (size_t)blockIdx.x * 256 + threadIdx.x;
    const float4 v = ((const float4*)x)[i];
    float4 r; r.x = tf32r(v.x); r.y = tf32r(v.y); r.z = tf32r(v.z); r.w = tf32r(v.w);
    ((float4*)xt)[i] = r;
}

// ---------------- beta = sigmoid(x@w_b); g = -exp(a_log)*softplus(x@w_a+dt)
__global__ __launch_bounds__(256) void kc_beta_g(
    const float* __restrict__ x, const float* __restrict__ wb,
    const float* __restrict__ wa, const float* __restrict__ dtb,
    const float* __restrict__ alog, float* __restrict__ beta, float* __restrict__ g)
{
    __shared__ float xs[4*HID_];
    const int r0 = blockIdx.x * 4;
    for (int t = threadIdx.x; t < 4*HID_; t += 256)
        xs[t] = x[(size_t)r0*HID_ + t];
    __syncthreads();
    const int row = threadIdx.x >> 6, j = threadIdx.x & 63, col = j & 31;
    const float* w = (j < 32) ? wb : wa;
    float acc = 0.f;
    const float* xr = xs + row*HID_;
    for (int k = 0; k < HID_; k++) acc = fmaf(xr[k], w[(size_t)k*32+col], acc);
    const size_t oi = (size_t)(r0+row)*NVH_ + col;
    if (j < 32) beta[oi] = 1.f/(1.f+expf(-acc));
    else {
        float aa = acc + dtb[col];
        float sp = fmaxf(aa,0.f) + log1pf(expf(-fabsf(aa)));
        g[oi] = -expf(alog[col]) * sp;
    }
}

// ---------------- causal depthwise conv (KS=4) + silu ---------------------
__global__ __launch_bounds__(256) void kd_conv(
    const float* __restrict__ lin, const float* __restrict__ cw, float* __restrict__ out)
{
    const size_t idx = (size_t)blockIdx.x*256 + threadIdx.x;
    const int d4 = (int)(idx & (CONV_/4 - 1));
    const size_t bs = idx >> 11;
    const int s = (int)(bs & (S_-1));
    const int d0 = d4*4;
    float w0[4],w1[4],w2[4],w3[4];
    *(float4*)w0 = ((const float4*)cw)[d0+0];
    *(float4*)w1 = ((const float4*)cw)[d0+1];
    *(float4*)w2 = ((const float4*)cw)[d0+2];
    *(float4*)w3 = ((const float4*)cw)[d0+3];
    float a0=0,a1=0,a2=0,a3=0;
    #pragma unroll
    for (int t=0;t<4;t++) {
        if (s-3+t >= 0) {
            const float4 xv = *(const float4*)(lin + (bs+t-3)*CONV_ + d0);
            a0=fmaf(xv.x,w0[t],a0); a1=fmaf(xv.y,w1[t],a1);
            a2=fmaf(xv.z,w2[t],a2); a3=fmaf(xv.w,w3[t],a3);
        }
    }
    float4 r; r.x=siluf(a0); r.y=siluf(a1); r.z=siluf(a2); r.w=siluf(a3);
    ((float4*)out)[idx] = r;
}

// ---------------- per-chunk precompute ------------------------------------
constexpr int KE_SMEM = (3*64*129 + 64*64 + 64*65 + 192) * 4;
__global__ __launch_bounds__(256) void ke_pre(
    const float* __restrict__ conv, const float* __restrict__ betag,
    const float* __restrict__ gin, float* __restrict__ qg, float* __restrict__ kdo,
    float* __restrict__ vco, float* __restrict__ kcdo, float* __restrict__ attnl,
    float* __restrict__ glasto)
{
    extern __shared__ float sm[];
    float* q_s  = sm;
    float* k_s  = q_s + 64*129;
    float* vb_s = k_s + 64*129;
    float* A_s  = vb_s + 64*129;
    float* T_s  = A_s + 64*64;
    float* gc_s = T_s + 64*65;
    float* be_s = gc_s + 64;
    float* w_s  = be_s + 64;
    const int blk = blockIdx.x;
    const int n = blk & 63, h = (blk>>6) & 31, b = blk >> 11, kh = h >> 1;
    const int s0 = n*64, tid = threadIdx.x;
    const size_t rowbase = ((size_t)(b*S_)+s0)*CONV_;
    for (int t = tid; t < 64*128; t += 256) {
        const int i = t>>7, c = t&127;
        const size_t base = rowbase + (size_t)i*CONV_;
        q_s [i*129+c] = conv[base + kh*128 + c];
        k_s [i*129+c] = conv[base + KEY_ + kh*128 + c];
        vb_s[i*129+c] = conv[base + 2*KEY_ + h*128 + c];
    }
    if (tid < 64) {
        const size_t gi = ((size_t)(b*S_)+s0+tid)*NVH_ + h;
        be_s[tid] = betag[gi];
        gc_s[tid] = gin[gi];
    }
    __syncthreads();
    if (tid == 0) {
        float run = 0.f;
        for (int i = 0; i < 64; i++) { run += gc_s[i]; gc_s[i] = run; }
        glasto[blk] = run;
    }
    __syncthreads();
    {
        const int warp = tid >> 5, lane = tid & 31;
        for (int rr = 0; rr < 8; rr++) {
            const int i = warp*8 + rr;
            float qv[4], kv[4]; float sq=0.f, sk=0.f;
            #pragma unroll
            for (int u=0;u<4;u++){
                const int c = lane + u*32;
                qv[u]=q_s[i*129+c]; kv[u]=k_s[i*129+c];
                sq=fmaf(qv[u],qv[u],sq); sk=fmaf(kv[u],kv[u],sk);
            }
            #pragma unroll
            for (int off=16; off; off>>=1) {
                sq += __shfl_xor_sync(0xffffffffu, sq, off);
                sk += __shfl_xor_sync(0xffffffffu, sk, off);
            }
            const float iq = rsqrtf(sq+1e-6f)*0.08838834764831845f;
            const float ik = rsqrtf(sk+1e-6f);
            #pragma unroll
            for (int u=0;u<4;u++){
                const int c = lane + u*32;
                q_s[i*129+c]=qv[u]*iq; k_s[i*129+c]=kv[u]*ik;
            }
        }
    }
    for (int t = tid; t < 64*128; t += 256) {
        const int i = t>>7, c = t&127;
        vb_s[i*129+c] *= be_s[i];
    }
    for (int t = tid; t < 64*65; t += 256) T_s[t] = 0.f;
    if (tid < 64) w_s[tid] = be_s[tid]*expf(gc_s[tid]);
    __syncthreads();
    {
        const int ti = tid >> 4, tj = tid & 15;
        const int i0 = ti*4, j0 = tj*4;
        float dk[4][4], dq[4][4];
        #pragma unroll
        for (int r=0;r<4;r++){
            #pragma unroll
            for(int u=0;u<4;u++){dk[r][u]=0.f;dq[r][u]=0.f;} }
        for (int c = 0; c < 128; c++) {
            float ki[4],qi[4],kj[4];
            #pragma unroll
            for (int r=0;r<4;r++){ ki[r]=k_s[(i0+r)*129+c]; qi[r]=q_s[(i0+r)*129+c]; kj[r]=k_s[(j0+r)*129+c]; }
            #pragma unroll
            for (int r=0;r<4;r++){
                #pragma unroll
                for(int u=0;u<4;u++){ dk[r][u]=fmaf(ki[r],kj[u],dk[r][u]); dq[r][u]=fmaf(qi[r],kj[u],dq[r][u]); } }
        }
        const size_t ab = (size_t)blk*4096;
        #pragma unroll
        for (int r=0;r<4;r++){
            #pragma unroll
            for (int u=0;u<4;u++){
                const int i=i0+r, j=j0+u;
                const float dec = (i>=j) ? expf(gc_s[i]-gc_s[j]) : 0.f;
                A_s[i*64+j] = (i>j) ? (-be_s[i]*dk[r][u]*dec) : 0.f;
                attnl[ab + i*64 + j] = (i>=j) ? dq[r][u]*dec : 0.f;
            }
        }
    }
    __syncthreads();
    if (tid < 64) {
        const int col = tid;
        T_s[col*65+col] = 1.f;
        for (int i = col+1; i < 64; i++) {
            float acc = 0.f;
            for (int j = col; j < i; j++) acc = fmaf(A_s[i*64+j], T_s[j*65+col], acc);
            T_s[i*65+col] = acc;
        }
    }
    __syncthreads();
    {
        const int it = tid >> 4, ct = tid & 15;
        const int i0 = it*4, c0 = ct*8;
        float avc[4][8], akc[4][8];
        #pragma unroll
        for (int r=0;r<4;r++){
            #pragma unroll
            for(int u=0;u<8;u++){avc[r][u]=0.f;akc[r][u]=0.f;} }
        for (int j = 0; j < 64; j++) {
            float tj4[4], tw4[4];
            const float wj = w_s[j];
            #pragma unroll
            for (int r=0;r<4;r++){ tj4[r]=T_s[(i0+r)*65+j]; tw4[r]=tj4[r]*wj; }
            #pragma unroll
            for (int u=0;u<8;u++){
                const float vbv = vb_s[j*129+c0+u];
                const float kv  = k_s [j*129+c0+u];
                #pragma unroll
                for (int r=0;r<4;r++){
                    avc[r][u]=fmaf(tj4[r],vbv,avc[r][u]);
                    akc[r][u]=fmaf(tw4[r],kv ,akc[r][u]);
                }
            }
        }
        const size_t cb = (size_t)blk*8192;
        #pragma unroll
        for (int r=0;r<4;r++){
            #pragma unroll
            for (int u=0;u<8;u++){
                vco [cb + (i0+r)*128 + c0+u] = avc[r][u];
                kcdo[cb + (i0+r)*128 + c0+u] = akc[r][u];
            }
        }
    }
    {
        const float gl = gc_s[63];
        const size_t cb = (size_t)blk*8192;
        for (int t = tid; t < 64*128; t += 256) {
            const int i = t>>7, c = t&127;
            qg [cb+t] = q_s[i*129+c]*expf(gc_s[i]);
            kdo[cb+t] = k_s[i*129+c]*expf(gl-gc_s[i]);
        }
    }
}

// ---------------- persistent V-split scan (128 CTAs) ----------------------
constexpr int SCAN_SMEM = (128*64 + 3*64*128 + 2*64*64) * 4;
__global__ __launch_bounds__(256) void kf_scan(
    const float* __restrict__ qg, const float* __restrict__ kcd,
    const float* __restrict__ kd, const float* __restrict__ vc,
    const float* __restrict__ attn, const float* __restrict__ glast,
    float* __restrict__ o)
{
    extern __shared__ float sm[];
    float* st    = sm;
    float* qg_s  = st + 8192;
    float* kcd_s = qg_s + 8192;
    float* kd_s  = kcd_s + 8192;
    float* at_s  = kd_s + 8192;
    float* vn_s  = at_s + 4096;
    const int cta = blockIdx.x, vh = cta & 1, bh = cta >> 1;
    const int tid = threadIdx.x;
    const int ti = tid >> 4, tj = tid & 15;
    const int i0 = ti*4, c0 = tj*4, k0 = ti*8;
    for (int t = tid; t < 8192; t += 256) st[t] = 0.f;
    __syncthreads();
    for (int n = 0; n < 64; n++) {
        const size_t blk = (size_t)(bh*64 + n);
        const float4* qgg = (const float4*)(qg + blk*8192);
        const float4* kcg = (const float4*)(kcd + blk*8192);
        const float4* kdg = (const float4*)(kd + blk*8192);
        for (int t = tid; t < 2048; t += 256) {
            ((float4*)qg_s)[t]=qgg[t]; ((float4*)kcd_s)[t]=kcg[t]; ((float4*)kd_s)[t]=kdg[t];
        }
        const float4* atg = (const float4*)(attn + blk*4096);
        for (int t = tid; t < 1024; t += 256) ((float4*)at_s)[t] = atg[t];
        for (int t = tid; t < 1024; t += 256) {
            const int i = t>>4, cg = (t&15)*4;
            *(float4*)(vn_s + i*64 + cg) = *(const float4*)(vc + blk*8192 + i*128 + vh*64 + cg);
        }
        __syncthreads();
        float ov[4][4], vv[4][4];
        #pragma unroll
        for (int r=0;r<4;r++){
            #pragma unroll
            for(int u=0;u<4;u++){ov[r][u]=0.f;vv[r][u]=0.f;} }
        for (int k = 0; k < 128; k++) {
            const float4 sv = *(const float4*)&st[k*64 + c0];
            #pragma unroll
            for (int r=0;r<4;r++) {
                const float kq = qg_s[(i0+r)*128+k];
                const float kc = kcd_s[(i0+r)*128+k];
                ov[r][0]=fmaf(kq,sv.x,ov[r][0]); ov[r][1]=fmaf(kq,sv.y,ov[r][1]);
                ov[r][2]=fmaf(kq,sv.z,ov[r][2]); ov[r][3]=fmaf(kq,sv.w,ov[r][3]);
                vv[r][0]=fmaf(kc,sv.x,vv[r][0]); vv[r][1]=fmaf(kc,sv.y,vv[r][1]);
                vv[r][2]=fmaf(kc,sv.z,vv[r][2]); vv[r][3]=fmaf(kc,sv.w,vv[r][3]);
            }
        }
        #pragma unroll
        for (int r=0;r<4;r++){
            #pragma unroll
            for(int u=0;u<4;u++) vn_s[(i0+r)*64 + c0+u] -= vv[r][u]; }
        __syncthreads();
        for (int j = 0; j < 64; j++) {
            const float4 vj = *(const float4*)&vn_s[j*64 + c0];
            #pragma unroll
            for (int r=0;r<4;r++) {
                const float a = at_s[(i0+r)*64+j];
                ov[r][0]=fmaf(a,vj.x,ov[r][0]); ov[r][1]=fmaf(a,vj.y,ov[r][1]);
                ov[r][2]=fmaf(a,vj.z,ov[r][2]); ov[r][3]=fmaf(a,vj.w,ov[r][3]);
            }
        }
        float* og = o + blk*8192 + vh*64;
        #pragma unroll
        for (int r=0;r<4;r++)
            *(float4*)(og + (i0+r)*128 + c0) = make_float4(ov[r][0],ov[r][1],ov[r][2],ov[r][3]);
        const float eg = expf(glast[blk]);
        float sa[8][4];
        #pragma unroll
        for (int r=0;r<8;r++){
            #pragma unroll
            for(int u=0;u<4;u++) sa[r][u]=0.f; }
        for (int i = 0; i < 64; i++) {
            const float4 vi = *(const float4*)&vn_s[i*64 + c0];
            #pragma unroll
            for (int r=0;r<8;r++) {
                const float kv = kd_s[i*128 + k0 + r];
                sa[r][0]=fmaf(kv,vi.x,sa[r][0]); sa[r][1]=fmaf(kv,vi.y,sa[r][1]);
                sa[r][2]=fmaf(kv,vi.z,sa[r][2]); sa[r][3]=fmaf(kv,vi.w,sa[r][3]);
            }
        }
        #pragma unroll
        for (int r=0;r<8;r++){
            #pragma unroll
            for (int u=0;u<4;u++) {
                float* p = &st[(k0+r)*64 + c0+u];
                *p = (*p)*eg + sa[r][u];
            }
        }
        __syncthreads();
    }
}

// ---------------- gated RMSNorm (writes tf32-rounded y) -------------------
__global__ __launch_bounds__(256) void kg_norm(
    const float* __restrict__ o, const float* __restrict__ z,
    const float* __restrict__ nw, float* __restrict__ y)
{
    const int gw = (blockIdx.x*256 + threadIdx.x) >> 5;
    const int lane = threadIdx.x & 31;
    const int h = gw & 31, bs = gw >> 5;
    const int b = bs >> 12, s = bs & 4095;
    const size_t oi = (((size_t)(b*32+h)*64 + (s>>6))*64 + (s&63))*128;
    const float4 cv = *(const float4*)(o + oi + lane*4);
    float ss = cv.x*cv.x + cv.y*cv.y + cv.z*cv.z + cv.w*cv.w;
    #pragma unroll
    for (int off=16; off; off>>=1) ss += __shfl_xor_sync(0xffffffffu, ss, off);
    const float inv = rsqrtf(ss*(1.f/128.f) + 1e-6f);
    const float4 zv = *(const float4*)(z + (size_t)bs*4096 + h*128 + lane*4);
    const float4 w  = *(const float4*)(nw + lane*4);
    float4 r;
    r.x = tf32r(cv.x*inv*w.x*siluf(zv.x)); r.y = tf32r(cv.y*inv*w.y*siluf(zv.y));
    r.z = tf32r(cv.z*inv*w.z*siluf(zv.z)); r.w = tf32r(cv.w*inv*w.w*siluf(zv.w));
    *(float4*)(y + (size_t)bs*4096 + h*128 + lane*4) = r;
}

// ---------------- launch ----------------------------------------------------
extern "C" void kernel_launch(void* const* d_in, const int* in_sizes, int n_in,
                              void* d_out, int out_size)
{
    const float* x     = (const float*)d_in[0];
    const float* w_qkv = (const float*)d_in[1];
    const float* w_z   = (const float*)d_in[2];
    const float* w_b   = (const float*)d_in[3];
    const float* w_a   = (const float*)d_in[4];
    const float* cw    = (const float*)d_in[5];
    const float* dtb   = (const float*)d_in[6];
    const float* alog  = (const float*)d_in[7];
    const float* nw    = (const float*)d_in[8];
    const float* w_out = (const float*)d_in[9];
    float* out = (float*)d_out;

    float *lin,*conv,*z,*beta,*gg,*qg,*kdd,*vc,*kcd,*attn,*glast,*o,*y,*xt,*wqkvT,*wzT,*woutT;
    cudaGetSymbolAddress((void**)&lin,  g_lin);
    cudaGetSymbolAddress((void**)&conv, g_conv);
    cudaGetSymbolAddress((void**)&z,    g_z);
    cudaGetSymbolAddress((void**)&beta, g_beta);
    cudaGetSymbolAddress((void**)&gg,   g_gg);
    cudaGetSymbolAddress((void**)&qg,   g_qg);
    cudaGetSymbolAddress((void**)&kdd,  g_kdd);
    cudaGetSymbolAddress((void**)&vc,   g_vc);
    cudaGetSymbolAddress((void**)&kcd,  g_kcd);
    cudaGetSymbolAddress((void**)&attn, g_attn);
    cudaGetSymbolAddress((void**)&glast,g_glast);
    cudaGetSymbolAddress((void**)&o,    g_o);
    cudaGetSymbolAddress((void**)&y,    g_y);
    cudaGetSymbolAddress((void**)&xt,   g_xt);
    cudaGetSymbolAddress((void**)&wqkvT,g_wqkvT);
    cudaGetSymbolAddress((void**)&wzT,  g_wzT);
    cudaGetSymbolAddress((void**)&woutT,g_woutT);

    cudaFuncSetAttribute(ke_pre,  cudaFuncAttributeMaxDynamicSharedMemorySize, KE_SMEM);
    cudaFuncSetAttribute(kf_scan, cudaFuncAttributeMaxDynamicSharedMemorySize, SCAN_SMEM);

    kt_trans<<<dim3(CONV_/32, HID_/32), 256>>>(w_qkv, wqkvT, HID_, CONV_);
    kt_trans<<<dim3(VAL_/32,  HID_/32), 256>>>(w_z,   wzT,   HID_, VAL_);
    kt_trans<<<dim3(HID_/32,  VAL_/32), 256>>>(w_out, woutT, VAL_, HID_);
    kt_round<<<(MROWS*HID_)/1024, 256>>>(x, xt);

    gemm_mma<<<dim3(CONV_/128, MROWS/128), 256>>>(xt, wqkvT, lin, MROWS, CONV_, HID_);
    gemm_mma<<<dim3(VAL_/128,  MROWS/128), 256>>>(xt, wzT,   z,   MROWS, VAL_, HID_);
    kc_beta_g<<<MROWS/4, 256>>>(x, w_b, w_a, dtb, alog, beta, gg);
    kd_conv<<<(MROWS*(CONV_/4))/256, 256>>>(lin, cw, conv);
    ke_pre<<<4096, 256, KE_SMEM>>>(conv, beta, gg, qg, kdd, vc, kcd, attn, glast);
    kf_scan<<<128, 256, SCAN_SMEM>>>(qg, kcd, kdd, vc, attn, glast, o);
    kg_norm<<<(MROWS*NVH_)/8, 256>>>(o, z, nw, y);
    gemm_mma<<<dim3(HID_/128, MROWS/128), 256>>>(y, woutT, out, MROWS, HID_, VAL_);
}

// round 6
// speedup vs baseline: 1.7618x; 1.5495x over previous
#include <cuda_runtime.h>
#include <math.h>
#include <stdint.h>

constexpr int B_ = 2, S_ = 4096, HID_ = 2048, NVH_ = 32;
constexpr int CONV_ = 8192, KEY_ = 2048, VAL_ = 4096;
constexpr int NC_ = 64, BH_ = 64, MROWS = 8192;

static __device__ float g_lin  [(size_t)MROWS*CONV_];
static __device__ float g_conv [(size_t)MROWS*CONV_];
static __device__ float g_z    [(size_t)MROWS*VAL_];
static __device__ float g_beta [(size_t)MROWS*NVH_];
static __device__ float g_gg   [(size_t)MROWS*NVH_];
static __device__ float g_qg   [(size_t)BH_*S_*128];
static __device__ float g_kdd  [(size_t)BH_*S_*128];
static __device__ float g_vc   [(size_t)BH_*S_*128];
static __device__ float g_kcd  [(size_t)BH_*S_*128];
static __device__ float g_attn [(size_t)BH_*NC_*64*64];
static __device__ float g_glast[BH_*NC_];
static __device__ float g_o    [(size_t)BH_*S_*128];
static __device__ float g_y    [(size_t)MROWS*VAL_];
static __device__ float g_xt   [(size_t)MROWS*HID_];
static __device__ float g_wqkvT[(size_t)CONV_*HID_];
static __device__ float g_wzT  [(size_t)VAL_*HID_];
static __device__ float g_woutT[(size_t)HID_*VAL_];

__device__ __forceinline__ float siluf(float v){ return v / (1.f + expf(-v)); }
__device__ __forceinline__ float tf32r(float v){
    uint32_t o; asm("cvt.rna.tf32.f32 %0, %1;" : "=r"(o) : "f"(v));
    return __uint_as_float(o);
}
__device__ __forceinline__ void mma_tf32(float* c, const uint32_t* a, const uint32_t* b){
    asm volatile("mma.sync.aligned.m16n8k8.row.col.f32.tf32.tf32.f32 "
        "{%0,%1,%2,%3}, {%4,%5,%6,%7}, {%8,%9}, {%0,%1,%2,%3};"
        : "+f"(c[0]), "+f"(c[1]), "+f"(c[2]), "+f"(c[3])
        : "r"(a[0]), "r"(a[1]), "r"(a[2]), "r"(a[3]), "r"(b[0]), "r"(b[1]));
}

// ------- tf32 mma.sync GEMM: C[M,N] = A[M,K] @ Bt[N,K]^T, 128x128x16 ------
__global__ __launch_bounds__(256) void gemm_mma(
    const float* __restrict__ A, const float* __restrict__ Bt,
    float* __restrict__ C, int M, int N, int K)
{
    __shared__ float As[2][128][20];
    __shared__ float Bs[2][128][20];
    const int tid = threadIdx.x;
    const int bx = blockIdx.x * 128, by = blockIdx.y * 128;
    const int warp = tid >> 5, lane = tid & 31;
    const int gid = lane >> 2, tig = lane & 3;
    const int wm = (warp >> 2) * 64;      // 0 or 64
    const int wn = (warp & 3) * 32;       // 0,32,64,96
    const int lrow = tid >> 2;            // 0..63
    const int lk   = (tid & 3) * 4;       // 0,4,8,12
    const float* Ag = A  + (size_t)(by + lrow) * K + lk;
    const float* Bg = Bt + (size_t)(bx + lrow) * K + lk;
    const int NT = K >> 4;

    float acc[4][4][4];
    #pragma unroll
    for (int mt=0;mt<4;mt++){
        #pragma unroll
        for (int nt=0;nt<4;nt++){
            #pragma unroll
            for (int u=0;u<4;u++) acc[mt][nt][u]=0.f; } }

    float4 pa0 = *(const float4*)(Ag);
    float4 pa1 = *(const float4*)(Ag + (size_t)64 * K);
    float4 pb0 = *(const float4*)(Bg);
    float4 pb1 = *(const float4*)(Bg + (size_t)64 * K);
    *(float4*)&As[0][lrow   ][lk] = pa0;
    *(float4*)&As[0][lrow+64][lk] = pa1;
    *(float4*)&Bs[0][lrow   ][lk] = pb0;
    *(float4*)&Bs[0][lrow+64][lk] = pb1;
    __syncthreads();

    for (int kc = 0; kc < NT; kc++) {
        const int cur = kc & 1, nxt = cur ^ 1;
        if (kc + 1 < NT) {
            const float* A2 = Ag + (kc+1)*16;
            const float* B2 = Bg + (kc+1)*16;
            pa0 = *(const float4*)(A2);
            pa1 = *(const float4*)(A2 + (size_t)64 * K);
            pb0 = *(const float4*)(B2);
            pb1 = *(const float4*)(B2 + (size_t)64 * K);
        }
        #pragma unroll
        for (int kk = 0; kk < 2; kk++) {
            const int kb = kk * 8;
            uint32_t af[4][4], bf[4][2];
            #pragma unroll
            for (int mt = 0; mt < 4; mt++) {
                const int r = wm + mt*16 + gid;
                af[mt][0] = __float_as_uint(As[cur][r  ][kb + tig]);
                af[mt][1] = __float_as_uint(As[cur][r+8][kb + tig]);
                af[mt][2] = __float_as_uint(As[cur][r  ][kb + tig + 4]);
                af[mt][3] = __float_as_uint(As[cur][r+8][kb + tig + 4]);
            }
            #pragma unroll
            for (int nt = 0; nt < 4; nt++) {
                const int n = wn + nt*8 + gid;
                bf[nt][0] = __float_as_uint(Bs[cur][n][kb + tig]);
                bf[nt][1] = __float_as_uint(Bs[cur][n][kb + tig + 4]);
            }
            #pragma unroll
            for (int mt = 0; mt < 4; mt++){
                #pragma unroll
                for (int nt = 0; nt < 4; nt++)
                    mma_tf32(acc[mt][nt], af[mt], bf[nt]);
            }
        }
        if (kc + 1 < NT) {
            *(float4*)&As[nxt][lrow   ][lk] = pa0;
            *(float4*)&As[nxt][lrow+64][lk] = pa1;
            *(float4*)&Bs[nxt][lrow   ][lk] = pb0;
            *(float4*)&Bs[nxt][lrow+64][lk] = pb1;
        }
        __syncthreads();
    }

    #pragma unroll
    for (int mt = 0; mt < 4; mt++) {
        const int r0 = by + wm + mt*16 + gid;
        #pragma unroll
        for (int nt = 0; nt < 4; nt++) {
            const int cc = bx + wn + nt*8 + tig*2;
            *(float2*)(C + (size_t)r0 * N + cc)     = make_float2(acc[mt][nt][0], acc[mt][nt][1]);
            *(float2*)(C + (size_t)(r0+8) * N + cc) = make_float2(acc[mt][nt][2], acc[mt][nt][3]);
        }
    }
}

// ---------------- weight transpose + tf32 round: w[K,N] -> wt[N,K] --------
__global__ __launch_bounds__(256) void kt_trans(
    const float* __restrict__ w, float* __restrict__ wt, int K, int N)
{
    __shared__ float t[32][33];
    const int tx = threadIdx.x & 31, ty = threadIdx.x >> 5;
    const int n0 = blockIdx.x * 32, k0 = blockIdx.y * 32;
    #pragma unroll
    for (int r = 0; r < 4; r++)
        t[ty + r*8][tx] = w[(size_t)(k0 + ty + r*8) * N + n0 + tx];
    __syncthreads();
    #pragma unroll
    for (int r = 0; r < 4; r++)
        wt[(size_t)(n0 + ty + r*8) * K + k0 + tx] = tf32r(t[tx][ty + r*8]);
}

// ---------------- tf32 round x --------------------------------------------
__global__ __launch_bounds__(256) void kt_round(const float* __restrict__ x, float* __restrict__ xt)
{
    const size_t i = (size_t)blockIdx.x * 256 + threadIdx.x;
    const float4 v = ((const float4*)x)[i];
    float4 r; r.x = tf32r(v.x); r.y = tf32r(v.y); r.z = tf32r(v.z); r.w = tf32r(v.w);
    ((float4*)xt)[i] = r;
}

// ---------------- beta = sigmoid(x@w_b); g = -exp(a_log)*softplus(x@w_a+dt)
__global__ __launch_bounds__(256) void kc_beta_g(
    const float* __restrict__ x, const float* __restrict__ wb,
    const float* __restrict__ wa, const float* __restrict__ dtb,
    const float* __restrict__ alog, float* __restrict__ beta, float* __restrict__ g)
{
    __shared__ float xs[4*HID_];
    const int r0 = blockIdx.x * 4;
    for (int t = threadIdx.x; t < 4*HID_; t += 256)
        xs[t] = x[(size_t)r0*HID_ + t];
    __syncthreads();
    const int row = threadIdx.x >> 6, j = threadIdx.x & 63, col = j & 31;
    const float* w = (j < 32) ? wb : wa;
    float acc = 0.f;
    const float* xr = xs + row*HID_;
    for (int k = 0; k < HID_; k++) acc = fmaf(xr[k], w[(size_t)k*32+col], acc);
    const size_t oi = (size_t)(r0+row)*NVH_ + col;
    if (j < 32) beta[oi] = 1.f/(1.f+expf(-acc));
    else {
        float aa = acc + dtb[col];
        float sp = fmaxf(aa,0.f) + log1pf(expf(-fabsf(aa)));
        g[oi] = -expf(alog[col]) * sp;
    }
}

// ---------------- causal depthwise conv (KS=4) + silu ---------------------
__global__ __launch_bounds__(256) void kd_conv(
    const float* __restrict__ lin, const float* __restrict__ cw, float* __restrict__ out)
{
    const size_t idx = (size_t)blockIdx.x*256 + threadIdx.x;
    const int d4 = (int)(idx & (CONV_/4 - 1));
    const size_t bs = idx >> 11;
    const int s = (int)(bs & (S_-1));
    const int d0 = d4*4;
    float w0[4],w1[4],w2[4],w3[4];
    *(float4*)w0 = ((const float4*)cw)[d0+0];
    *(float4*)w1 = ((const float4*)cw)[d0+1];
    *(float4*)w2 = ((const float4*)cw)[d0+2];
    *(float4*)w3 = ((const float4*)cw)[d0+3];
    float a0=0,a1=0,a2=0,a3=0;
    #pragma unroll
    for (int t=0;t<4;t++) {
        if (s-3+t >= 0) {
            const float4 xv = *(const float4*)(lin + (bs+t-3)*CONV_ + d0);
            a0=fmaf(xv.x,w0[t],a0); a1=fmaf(xv.y,w1[t],a1);
            a2=fmaf(xv.z,w2[t],a2); a3=fmaf(xv.w,w3[t],a3);
        }
    }
    float4 r; r.x=siluf(a0); r.y=siluf(a1); r.z=siluf(a2); r.w=siluf(a3);
    ((float4*)out)[idx] = r;
}

// ---------------- per-chunk precompute ------------------------------------
constexpr int KE_SMEM = (3*64*129 + 64*64 + 64*65 + 192) * 4;
__global__ __launch_bounds__(256) void ke_pre(
    const float* __restrict__ conv, const float* __restrict__ betag,
    const float* __restrict__ gin, float* __restrict__ qg, float* __restrict__ kdo,
    float* __restrict__ vco, float* __restrict__ kcdo, float* __restrict__ attnl,
    float* __restrict__ glasto)
{
    extern __shared__ float sm[];
    float* q_s  = sm;
    float* k_s  = q_s + 64*129;
    float* vb_s = k_s + 64*129;
    float* A_s  = vb_s + 64*129;
    float* T_s  = A_s + 64*64;
    float* gc_s = T_s + 64*65;
    float* be_s = gc_s + 64;
    float* w_s  = be_s + 64;
    const int blk = blockIdx.x;
    const int n = blk & 63, h = (blk>>6) & 31, b = blk >> 11, kh = h >> 1;
    const int s0 = n*64, tid = threadIdx.x;
    const size_t rowbase = ((size_t)(b*S_)+s0)*CONV_;
    for (int t = tid; t < 64*128; t += 256) {
        const int i = t>>7, c = t&127;
        const size_t base = rowbase + (size_t)i*CONV_;
        q_s [i*129+c] = conv[base + kh*128 + c];
        k_s [i*129+c] = conv[base + KEY_ + kh*128 + c];
        vb_s[i*129+c] = conv[base + 2*KEY_ + h*128 + c];
    }
    if (tid < 64) {
        const size_t gi = ((size_t)(b*S_)+s0+tid)*NVH_ + h;
        be_s[tid] = betag[gi];
        gc_s[tid] = gin[gi];
    }
    __syncthreads();
    if (tid == 0) {
        float run = 0.f;
        for (int i = 0; i < 64; i++) { run += gc_s[i]; gc_s[i] = run; }
        glasto[blk] = run;
    }
    __syncthreads();
    {
        const int warp = tid >> 5, lane = tid & 31;
        for (int rr = 0; rr < 8; rr++) {
            const int i = warp*8 + rr;
            float qv[4], kv[4]; float sq=0.f, sk=0.f;
            #pragma unroll
            for (int u=0;u<4;u++){
                const int c = lane + u*32;
                qv[u]=q_s[i*129+c]; kv[u]=k_s[i*129+c];
                sq=fmaf(qv[u],qv[u],sq); sk=fmaf(kv[u],kv[u],sk);
            }
            #pragma unroll
            for (int off=16; off; off>>=1) {
                sq += __shfl_xor_sync(0xffffffffu, sq, off);
                sk += __shfl_xor_sync(0xffffffffu, sk, off);
            }
            const float iq = rsqrtf(sq+1e-6f)*0.08838834764831845f;
            const float ik = rsqrtf(sk+1e-6f);
            #pragma unroll
            for (int u=0;u<4;u++){
                const int c = lane + u*32;
                q_s[i*129+c]=qv[u]*iq; k_s[i*129+c]=kv[u]*ik;
            }
        }
    }
    for (int t = tid; t < 64*128; t += 256) {
        const int i = t>>7, c = t&127;
        vb_s[i*129+c] *= be_s[i];
    }
    for (int t = tid; t < 64*65; t += 256) T_s[t] = 0.f;
    if (tid < 64) w_s[tid] = be_s[tid]*expf(gc_s[tid]);
    __syncthreads();
    {
        const int ti = tid >> 4, tj = tid & 15;
        const int i0 = ti*4, j0 = tj*4;
        float dk[4][4], dq[4][4];
        #pragma unroll
        for (int r=0;r<4;r++){
            #pragma unroll
            for(int u=0;u<4;u++){dk[r][u]=0.f;dq[r][u]=0.f;} }
        for (int c = 0; c < 128; c++) {
            float ki[4],qi[4],kj[4];
            #pragma unroll
            for (int r=0;r<4;r++){ ki[r]=k_s[(i0+r)*129+c]; qi[r]=q_s[(i0+r)*129+c]; kj[r]=k_s[(j0+r)*129+c]; }
            #pragma unroll
            for (int r=0;r<4;r++){
                #pragma unroll
                for(int u=0;u<4;u++){ dk[r][u]=fmaf(ki[r],kj[u],dk[r][u]); dq[r][u]=fmaf(qi[r],kj[u],dq[r][u]); } }
        }
        const size_t ab = (size_t)blk*4096;
        #pragma unroll
        for (int r=0;r<4;r++){
            #pragma unroll
            for (int u=0;u<4;u++){
                const int i=i0+r, j=j0+u;
                const float dec = (i>=j) ? expf(gc_s[i]-gc_s[j]) : 0.f;
                A_s[i*64+j] = (i>j) ? (-be_s[i]*dk[r][u]*dec) : 0.f;
                attnl[ab + i*64 + j] = (i>=j) ? dq[r][u]*dec : 0.f;
            }
        }
    }
    __syncthreads();
    if (tid < 64) {
        const int col = tid;
        T_s[col*65+col] = 1.f;
        for (int i = col+1; i < 64; i++) {
            float acc = 0.f;
            for (int j = col; j < i; j++) acc = fmaf(A_s[i*64+j], T_s[j*65+col], acc);
            T_s[i*65+col] = acc;
        }
    }
    __syncthreads();
    {
        const int it = tid >> 4, ct = tid & 15;
        const int i0 = it*4, c0 = ct*8;
        float avc[4][8], akc[4][8];
        #pragma unroll
        for (int r=0;r<4;r++){
            #pragma unroll
            for(int u=0;u<8;u++){avc[r][u]=0.f;akc[r][u]=0.f;} }
        for (int j = 0; j < 64; j++) {
            float tj4[4], tw4[4];
            const float wj = w_s[j];
            #pragma unroll
            for (int r=0;r<4;r++){ tj4[r]=T_s[(i0+r)*65+j]; tw4[r]=tj4[r]*wj; }
            #pragma unroll
            for (int u=0;u<8;u++){
                const float vbv = vb_s[j*129+c0+u];
                const float kv  = k_s [j*129+c0+u];
                #pragma unroll
                for (int r=0;r<4;r++){
                    avc[r][u]=fmaf(tj4[r],vbv,avc[r][u]);
                    akc[r][u]=fmaf(tw4[r],kv ,akc[r][u]);
                }
            }
        }
        const size_t cb = (size_t)blk*8192;
        #pragma unroll
        for (int r=0;r<4;r++){
            #pragma unroll
            for (int u=0;u<8;u++){
                vco [cb + (i0+r)*128 + c0+u] = avc[r][u];
                kcdo[cb + (i0+r)*128 + c0+u] = akc[r][u];
            }
        }
    }
    {
        const float gl = gc_s[63];
        const size_t cb = (size_t)blk*8192;
        for (int t = tid; t < 64*128; t += 256) {
            const int i = t>>7, c = t&127;
            qg [cb+t] = q_s[i*129+c]*expf(gc_s[i]);
            kdo[cb+t] = k_s[i*129+c]*expf(gl-gc_s[i]);
        }
    }
}

// ---------------- persistent V-split scan (128 CTAs) ----------------------
constexpr int SCAN_SMEM = (128*64 + 3*64*128 + 2*64*64) * 4;
__global__ __launch_bounds__(256) void kf_scan(
    const float* __restrict__ qg, const float* __restrict__ kcd,
    const float* __restrict__ kd, const float* __restrict__ vc,
    const float* __restrict__ attn, const float* __restrict__ glast,
    float* __restrict__ o)
{
    extern __shared__ float sm[];
    float* st    = sm;
    float* qg_s  = st + 8192;
    float* kcd_s = qg_s + 8192;
    float* kd_s  = kcd_s + 8192;
    float* at_s  = kd_s + 8192;
    float* vn_s  = at_s + 4096;
    const int cta = blockIdx.x, vh = cta & 1, bh = cta >> 1;
    const int tid = threadIdx.x;
    const int ti = tid >> 4, tj = tid & 15;
    const int i0 = ti*4, c0 = tj*4, k0 = ti*8;
    for (int t = tid; t < 8192; t += 256) st[t] = 0.f;
    __syncthreads();
    for (int n = 0; n < 64; n++) {
        const size_t blk = (size_t)(bh*64 + n);
        const float4* qgg = (const float4*)(qg + blk*8192);
        const float4* kcg = (const float4*)(kcd + blk*8192);
        const float4* kdg = (const float4*)(kd + blk*8192);
        for (int t = tid; t < 2048; t += 256) {
            ((float4*)qg_s)[t]=qgg[t]; ((float4*)kcd_s)[t]=kcg[t]; ((float4*)kd_s)[t]=kdg[t];
        }
        const float4* atg = (const float4*)(attn + blk*4096);
        for (int t = tid; t < 1024; t += 256) ((float4*)at_s)[t] = atg[t];
        for (int t = tid; t < 1024; t += 256) {
            const int i = t>>4, cg = (t&15)*4;
            *(float4*)(vn_s + i*64 + cg) = *(const float4*)(vc + blk*8192 + i*128 + vh*64 + cg);
        }
        __syncthreads();
        float ov[4][4], vv[4][4];
        #pragma unroll
        for (int r=0;r<4;r++){
            #pragma unroll
            for(int u=0;u<4;u++){ov[r][u]=0.f;vv[r][u]=0.f;} }
        for (int k = 0; k < 128; k++) {
            const float4 sv = *(const float4*)&st[k*64 + c0];
            #pragma unroll
            for (int r=0;r<4;r++) {
                const float kq = qg_s[(i0+r)*128+k];
                const float kc = kcd_s[(i0+r)*128+k];
                ov[r][0]=fmaf(kq,sv.x,ov[r][0]); ov[r][1]=fmaf(kq,sv.y,ov[r][1]);
                ov[r][2]=fmaf(kq,sv.z,ov[r][2]); ov[r][3]=fmaf(kq,sv.w,ov[r][3]);
                vv[r][0]=fmaf(kc,sv.x,vv[r][0]); vv[r][1]=fmaf(kc,sv.y,vv[r][1]);
                vv[r][2]=fmaf(kc,sv.z,vv[r][2]); vv[r][3]=fmaf(kc,sv.w,vv[r][3]);
            }
        }
        #pragma unroll
        for (int r=0;r<4;r++){
            #pragma unroll
            for(int u=0;u<4;u++) vn_s[(i0+r)*64 + c0+u] -= vv[r][u]; }
        __syncthreads();
        for (int j = 0; j < 64; j++) {
            const float4 vj = *(const float4*)&vn_s[j*64 + c0];
            #pragma unroll
            for (int r=0;r<4;r++) {
                const float a = at_s[(i0+r)*64+j];
                ov[r][0]=fmaf(a,vj.x,ov[r][0]); ov[r][1]=fmaf(a,vj.y,ov[r][1]);
                ov[r][2]=fmaf(a,vj.z,ov[r][2]); ov[r][3]=fmaf(a,vj.w,ov[r][3]);
            }
        }
        float* og = o + blk*8192 + vh*64;
        #pragma unroll
        for (int r=0;r<4;r++)
            *(float4*)(og + (i0+r)*128 + c0) = make_float4(ov[r][0],ov[r][1],ov[r][2],ov[r][3]);
        const float eg = expf(glast[blk]);
        float sa[8][4];
        #pragma unroll
        for (int r=0;r<8;r++){
            #pragma unroll
            for(int u=0;u<4;u++) sa[r][u]=0.f; }
        for (int i = 0; i < 64; i++) {
            const float4 vi = *(const float4*)&vn_s[i*64 + c0];
            #pragma unroll
            for (int r=0;r<8;r++) {
                const float kv = kd_s[i*128 + k0 + r];
                sa[r][0]=fmaf(kv,vi.x,sa[r][0]); sa[r][1]=fmaf(kv,vi.y,sa[r][1]);
                sa[r][2]=fmaf(kv,vi.z,sa[r][2]); sa[r][3]=fmaf(kv,vi.w,sa[r][3]);
            }
        }
        #pragma unroll
        for (int r=0;r<8;r++){
            #pragma unroll
            for (int u=0;u<4;u++) {
                float* p = &st[(k0+r)*64 + c0+u];
                *p = (*p)*eg + sa[r][u];
            }
        }
        __syncthreads();
    }
}

// ---------------- gated RMSNorm (writes tf32-rounded y) -------------------
__global__ __launch_bounds__(256) void kg_norm(
    const float* __restrict__ o, const float* __restrict__ z,
    const float* __restrict__ nw, float* __restrict__ y)
{
    const int gw = (blockIdx.x*256 + threadIdx.x) >> 5;
    const int lane = threadIdx.x & 31;
    const int h = gw & 31, bs = gw >> 5;
    const int b = bs >> 12, s = bs & 4095;
    const size_t oi = (((size_t)(b*32+h)*64 + (s>>6))*64 + (s&63))*128;
    const float4 cv = *(const float4*)(o + oi + lane*4);
    float ss = cv.x*cv.x + cv.y*cv.y + cv.z*cv.z + cv.w*cv.w;
    #pragma unroll
    for (int off=16; off; off>>=1) ss += __shfl_xor_sync(0xffffffffu, ss, off);
    const float inv = rsqrtf(ss*(1.f/128.f) + 1e-6f);
    const float4 zv = *(const float4*)(z + (size_t)bs*4096 + h*128 + lane*4);
    const float4 w  = *(const float4*)(nw + lane*4);
    float4 r;
    r.x = tf32r(cv.x*inv*w.x*siluf(zv.x)); r.y = tf32r(cv.y*inv*w.y*siluf(zv.y));
    r.z = tf32r(cv.z*inv*w.z*siluf(zv.z)); r.w = tf32r(cv.w*inv*w.w*siluf(zv.w));
    *(float4*)(y + (size_t)bs*4096 + h*128 + lane*4) = r;
}

// ---------------- launch ----------------------------------------------------
extern "C" void kernel_launch(void* const* d_in, const int* in_sizes, int n_in,
                              void* d_out, int out_size)
{
    const float* x     = (const float*)d_in[0];
    const float* w_qkv = (const float*)d_in[1];
    const float* w_z   = (const float*)d_in[2];
    const float* w_b   = (const float*)d_in[3];
    const float* w_a   = (const float*)d_in[4];
    const float* cw    = (const float*)d_in[5];
    const float* dtb   = (const float*)d_in[6];
    const float* alog  = (const float*)d_in[7];
    const float* nw    = (const float*)d_in[8];
    const float* w_out = (const float*)d_in[9];
    float* out = (float*)d_out;

    float *lin,*conv,*z,*beta,*gg,*qg,*kdd,*vc,*kcd,*attn,*glast,*o,*y,*xt,*wqkvT,*wzT,*woutT;
    cudaGetSymbolAddress((void**)&lin,  g_lin);
    cudaGetSymbolAddress((void**)&conv, g_conv);
    cudaGetSymbolAddress((void**)&z,    g_z);
    cudaGetSymbolAddress((void**)&beta, g_beta);
    cudaGetSymbolAddress((void**)&gg,   g_gg);
    cudaGetSymbolAddress((void**)&qg,   g_qg);
    cudaGetSymbolAddress((void**)&kdd,  g_kdd);
    cudaGetSymbolAddress((void**)&vc,   g_vc);
    cudaGetSymbolAddress((void**)&kcd,  g_kcd);
    cudaGetSymbolAddress((void**)&attn, g_attn);
    cudaGetSymbolAddress((void**)&glast,g_glast);
    cudaGetSymbolAddress((void**)&o,    g_o);
    cudaGetSymbolAddress((void**)&y,    g_y);
    cudaGetSymbolAddress((void**)&xt,   g_xt);
    cudaGetSymbolAddress((void**)&wqkvT,g_wqkvT);
    cudaGetSymbolAddress((void**)&wzT,  g_wzT);
    cudaGetSymbolAddress((void**)&woutT,g_woutT);

    cudaFuncSetAttribute(ke_pre,  cudaFuncAttributeMaxDynamicSharedMemorySize, KE_SMEM);
    cudaFuncSetAttribute(kf_scan, cudaFuncAttributeMaxDynamicSharedMemorySize, SCAN_SMEM);

    kt_trans<<<dim3(CONV_/32, HID_/32), 256>>>(w_qkv, wqkvT, HID_, CONV_);
    kt_trans<<<dim3(VAL_/32,  HID_/32), 256>>>(w_z,   wzT,   HID_, VAL_);
    kt_trans<<<dim3(HID_/32,  VAL_/32), 256>>>(w_out, woutT, VAL_, HID_);
    kt_round<<<(MROWS*HID_)/1024, 256>>>(x, xt);

    gemm_mma<<<dim3(CONV_/128, MROWS/128), 256>>>(xt, wqkvT, lin, MROWS, CONV_, HID_);
    gemm_mma<<<dim3(VAL_/128,  MROWS/128), 256>>>(xt, wzT,   z,   MROWS, VAL_, HID_);
    kc_beta_g<<<MROWS/4, 256>>>(x, w_b, w_a, dtb, alog, beta, gg);
    kd_conv<<<(MROWS*(CONV_/4))/256, 256>>>(lin, cw, conv);
    ke_pre<<<4096, 256, KE_SMEM>>>(conv, beta, gg, qg, kdd, vc, kcd, attn, glast);
    kf_scan<<<128, 256, SCAN_SMEM>>>(qg, kcd, kdd, vc, attn, glast, o);
    kg_norm<<<(MROWS*NVH_)/8, 256>>>(o, z, nw, y);
    gemm_mma<<<dim3(HID_/128, MROWS/128), 256>>>(y, woutT, out, MROWS, HID_, VAL_);
}